// round 8
// baseline (speedup 1.0000x reference)
#include <cuda_runtime.h>
#include <cuda_bf16.h>

// Problem constants: N=150000 nodes, E=1e6 edges, D=64, 3 layers.
#define NMAX   150016
#define EMAX   1000448
#define DIM    64
#define SOFTEPS 1e-16f
#define NEGINF __int_as_float(0xff800000)

// Scratch (no allocations allowed -> __device__ globals).
__device__ float g_Z[NMAX * DIM];
__device__ float g_bufA[NMAX * DIM];
__device__ float g_bufB[NMAX * DIM];
__device__ float g_acc[NMAX * DIM];
__device__ float g_alphaP[EMAX];   // alpha, in dst-CSR order
// dst-CSR (gather-aggregate)
__device__ int g_cntD[NMAX], g_rsD[NMAX + 1], g_curD[NMAX];
__device__ int g_srcP[EMAX];       // src node at dst-CSR slot
// src-CSR (fused score+softmax)
__device__ int g_cntS[NMAX], g_rsS[NMAX + 1], g_curS[NMAX];
__device__ int   g_dstS[EMAX];     // dst node at src-CSR slot
__device__ int   g_posDS[EMAX];    // src-CSR slot -> dst-CSR slot
__device__ float g_eterm[EMAX];    // 64*exp(scale*ea[e]) at src-CSR slot
__device__ int g_bsumD[1024], g_bsumS[1024];

__device__ __forceinline__ const float* sel_cur(int sel, const float* emb_in) {
    if (sel == 0) return emb_in;
    return (sel == 1) ? g_bufA : g_bufB;
}
__device__ __forceinline__ float* sel_next(int sel) {
    return (sel == 1) ? g_bufA : g_bufB;
}
__device__ __forceinline__ int* csr_cnt(int w)  { return w ? g_cntS  : g_cntD; }
__device__ __forceinline__ int* csr_rs(int w)   { return w ? g_rsS   : g_rsD; }
__device__ __forceinline__ int* csr_cur(int w)  { return w ? g_curS  : g_curD; }
__device__ __forceinline__ int* csr_bsum(int w) { return w ? g_bsumS : g_bsumD; }

// ---------------- CSR build (once per launch) ----------------
__global__ void k_cnt_zero(int N) {
    int i = blockIdx.x * blockDim.x + threadIdx.x;
    if (i < N) { g_cntD[i] = 0; g_cntS[i] = 0; }
}
__global__ void k_hist(const int* __restrict__ ei, int E) {
    int e = blockIdx.x * blockDim.x + threadIdx.x;
    if (e < E) {
        atomicAdd(&g_cntD[ei[E + e]], 1);
        atomicAdd(&g_cntS[ei[e]], 1);
    }
}
__global__ void k_scan1(int which, int N) {
    __shared__ int sh[256];
    int* cnt = csr_cnt(which);
    int* rs  = csr_rs(which);
    int i = blockIdx.x * 256 + threadIdx.x;
    int v = (i < N) ? cnt[i] : 0;
    sh[threadIdx.x] = v;
    __syncthreads();
    for (int o = 1; o < 256; o <<= 1) {
        int t = (threadIdx.x >= o) ? sh[threadIdx.x - o] : 0;
        __syncthreads();
        sh[threadIdx.x] += t;
        __syncthreads();
    }
    if (i < N) rs[i] = sh[threadIdx.x] - v;
    if (threadIdx.x == 255) csr_bsum(which)[blockIdx.x] = sh[255];
}
__global__ void k_scan2(int which, int nb) {
    __shared__ int sh[1024];
    int* bs = csr_bsum(which);
    int t = threadIdx.x;
    int v = (t < nb) ? bs[t] : 0;
    sh[t] = v;
    __syncthreads();
    for (int o = 1; o < 1024; o <<= 1) {
        int u = (t >= o) ? sh[t - o] : 0;
        __syncthreads();
        sh[t] += u;
        __syncthreads();
    }
    if (t < nb) bs[t] = sh[t] - v;
}
__global__ void k_scan3(int which, int N, int E) {
    int i = blockIdx.x * blockDim.x + threadIdx.x;
    int* rs = csr_rs(which);
    if (i < N) {
        int r = rs[i] + csr_bsum(which)[i >> 8];
        rs[i] = r;
        csr_cur(which)[i] = r;
    }
    if (i == 0) rs[N] = E;
}
__global__ void k_scatter(const int* __restrict__ ei, const float* __restrict__ ea,
                          const float* __restrict__ scale_p, int E) {
    int e = blockIdx.x * blockDim.x + threadIdx.x;
    if (e >= E) return;
    int src = ei[e], dst = ei[E + e];
    int pd = atomicAdd(&g_curD[dst], 1);
    g_srcP[pd] = src;
    int ps = atomicAdd(&g_curS[src], 1);
    g_dstS[ps]  = dst;
    g_posDS[ps] = pd;
    g_eterm[ps] = 64.0f * __expf(scale_p[0] * ea[e]);
}

// ---------------- per-layer kernels ----------------
// Z = cur @ W : 32 rows / 256-thread block, 8 outputs per thread.
__global__ void k_gemm64(int curSel, const float* __restrict__ emb_in,
                         const float* __restrict__ W, int N) {
    __shared__ float sW[DIM * DIM];
    __shared__ float sX[32 * 65];
    const float* X = sel_cur(curSel, emb_in);
    int tid = threadIdx.x;
    #pragma unroll
    for (int i = tid; i < DIM * DIM; i += 256) sW[i] = W[i];
    int rowBase = blockIdx.x * 32;
    #pragma unroll
    for (int i = tid; i < 32 * DIM; i += 256) {
        int r = i >> 6, c = i & 63;
        int row = rowBase + r;
        sX[r * 65 + c] = (row < N) ? X[(size_t)row * DIM + c] : 0.0f;
    }
    __syncthreads();
    int r  = tid >> 3;
    int cg = (tid & 7) * 8;
    float a0=0,a1=0,a2=0,a3=0,a4=0,a5=0,a6=0,a7=0;
    #pragma unroll
    for (int k = 0; k < DIM; k++) {
        float xv = sX[r * 65 + k];
        float4 w0 = *(const float4*)&sW[k * DIM + cg];
        float4 w1 = *(const float4*)&sW[k * DIM + cg + 4];
        a0 = fmaf(xv, w0.x, a0); a1 = fmaf(xv, w0.y, a1);
        a2 = fmaf(xv, w0.z, a2); a3 = fmaf(xv, w0.w, a3);
        a4 = fmaf(xv, w1.x, a4); a5 = fmaf(xv, w1.y, a5);
        a6 = fmaf(xv, w1.z, a6); a7 = fmaf(xv, w1.w, a7);
    }
    int row = rowBase + r;
    if (row < N) {
        float4* o = (float4*)&g_Z[(size_t)row * DIM + cg];
        o[0] = make_float4(a0, a1, a2, a3);
        o[1] = make_float4(a4, a5, a6, a7);
    }
}

// Fused edge-score + segment-softmax: one warp per src node.
// 8-lane groups: 4 edges in flight per warp; each lane covers 8 floats.
// Group-scoped shuffle masks (trip counts differ by <=1 across groups).
__global__ void k_score_softmax(int curSel, const float* __restrict__ emb_in,
                                const float* __restrict__ bias_p, int N, int layer) {
    __shared__ float ssc[8][32];            // 8 warps/block
    int gt   = blockIdx.x * blockDim.x + threadIdx.x;
    int v    = gt >> 5;
    int lane = threadIdx.x & 31;
    int wid  = threadIdx.x >> 5;
    if (v >= N) return;
    int beg = g_rsS[v], end = g_rsS[v + 1];
    int deg = end - beg;
    if (deg == 0) return;
    const float* cur = sel_cur(curSel, emb_in);
    int q  = lane >> 3;                     // group 0..3 (edge stride 4)
    int ql = lane & 7;                      // lane in group; covers 8 floats
    unsigned gmask = 0xFFu << (q << 3);
    const float4* xrow = (const float4*)(cur + (size_t)v * DIM);
    float4 x0 = xrow[2 * ql];
    float4 x1 = xrow[2 * ql + 1];
    float bias = bias_p[layer];

    if (deg <= 32) {
        for (int t = q; t < deg; t += 4) {
            int j = beg + t;
            int dst = g_dstS[j];
            const float4* zrow = (const float4*)(g_Z + (size_t)dst * DIM);
            float4 z0 = zrow[2 * ql];
            float4 z1 = zrow[2 * ql + 1];
            float p = z0.x*x0.x + z0.y*x0.y + z0.z*x0.z + z0.w*x0.w
                    + z1.x*x1.x + z1.y*x1.y + z1.z*x1.z + z1.w*x1.w;
            #pragma unroll
            for (int o = 4; o; o >>= 1)
                p += __shfl_xor_sync(gmask, p, o, 8);
            float s = p + g_eterm[j] + bias;
            s = (s >= 0.0f) ? s : 0.2f * s;
            if (ql == 0) ssc[wid][t] = s;
        }
        __syncwarp();
        float sv = (lane < deg) ? ssc[wid][lane] : NEGINF;
        float m = sv;
        #pragma unroll
        for (int o = 16; o; o >>= 1)
            m = fmaxf(m, __shfl_xor_sync(0xffffffffu, m, o));
        float ex = (lane < deg) ? __expf(sv - m) : 0.0f;
        float den = ex;
        #pragma unroll
        for (int o = 16; o; o >>= 1)
            den += __shfl_xor_sync(0xffffffffu, den, o);
        if (lane < deg)
            g_alphaP[g_posDS[beg + lane]] = ex / (den + SOFTEPS);
    } else {
        // Rare fallback (deg>32): 3 passes, recompute.
        float mloc = NEGINF;
        for (int t = q; t < deg; t += 4) {
            int j = beg + t;
            int dst = g_dstS[j];
            const float4* zrow = (const float4*)(g_Z + (size_t)dst * DIM);
            float4 z0 = zrow[2 * ql];
            float4 z1 = zrow[2 * ql + 1];
            float p = z0.x*x0.x + z0.y*x0.y + z0.z*x0.z + z0.w*x0.w
                    + z1.x*x1.x + z1.y*x1.y + z1.z*x1.z + z1.w*x1.w;
            #pragma unroll
            for (int o = 4; o; o >>= 1)
                p += __shfl_xor_sync(gmask, p, o, 8);
            float s = p + g_eterm[j] + bias;
            s = (s >= 0.0f) ? s : 0.2f * s;
            mloc = fmaxf(mloc, s);
        }
        #pragma unroll
        for (int o = 16; o; o >>= 1)
            mloc = fmaxf(mloc, __shfl_xor_sync(0xffffffffu, mloc, o));
        float dloc = 0.0f;
        for (int t = q; t < deg; t += 4) {
            int j = beg + t;
            int dst = g_dstS[j];
            const float4* zrow = (const float4*)(g_Z + (size_t)dst * DIM);
            float4 z0 = zrow[2 * ql];
            float4 z1 = zrow[2 * ql + 1];
            float p = z0.x*x0.x + z0.y*x0.y + z0.z*x0.z + z0.w*x0.w
                    + z1.x*x1.x + z1.y*x1.y + z1.z*x1.z + z1.w*x1.w;
            #pragma unroll
            for (int o = 4; o; o >>= 1)
                p += __shfl_xor_sync(gmask, p, o, 8);
            float s = p + g_eterm[j] + bias;
            s = (s >= 0.0f) ? s : 0.2f * s;
            dloc += __expf(s - mloc);       // identical on all 8 lanes of group
        }
        #pragma unroll
        for (int o = 16; o; o >>= 1)
            dloc += __shfl_xor_sync(0xffffffffu, dloc, o);
        float den = dloc * 0.125f;          // /8 (each edge counted by 8 lanes)
        float inv = 1.0f / (den + SOFTEPS);
        for (int t = q; t < deg; t += 4) {
            int j = beg + t;
            int dst = g_dstS[j];
            const float4* zrow = (const float4*)(g_Z + (size_t)dst * DIM);
            float4 z0 = zrow[2 * ql];
            float4 z1 = zrow[2 * ql + 1];
            float p = z0.x*x0.x + z0.y*x0.y + z0.z*x0.z + z0.w*x0.w
                    + z1.x*x1.x + z1.y*x1.y + z1.z*x1.z + z1.w*x1.w;
            #pragma unroll
            for (int o = 4; o; o >>= 1)
                p += __shfl_xor_sync(gmask, p, o, 8);
            float s = p + g_eterm[j] + bias;
            s = (s >= 0.0f) ? s : 0.2f * s;
            if (ql == 0)
                g_alphaP[g_posDS[j]] = __expf(s - mloc) * inv;
        }
    }
}

// Gather-aggregate: 2 dst nodes per warp; 16-lane halves, float4 lanes,
// independent loops per half (no cross-half shuffles), unroll 2.
__global__ void k_aggregate(int curSel, const float* __restrict__ emb_in,
                            int nextSel, float* __restrict__ out,
                            int N, int layer) {
    int warp = (blockIdx.x * blockDim.x + threadIdx.x) >> 5;
    int half = (threadIdx.x >> 4) & 1;
    int hl   = threadIdx.x & 15;
    int v = warp * 2 + half;
    if (v >= N) return;
    const float* cur = sel_cur(curSel, emb_in);
    int beg = g_rsD[v];
    int end = g_rsD[v + 1];
    float4 acc = make_float4(0.f, 0.f, 0.f, 0.f);
    int j = beg;
    for (; j + 2 <= end; j += 2) {
        float al0 = g_alphaP[j];
        float al1 = g_alphaP[j + 1];
        int s0 = g_srcP[j];
        int s1 = g_srcP[j + 1];
        float4 a = ((const float4*)(cur + (size_t)s0 * DIM))[hl];
        float4 b = ((const float4*)(cur + (size_t)s1 * DIM))[hl];
        acc.x = fmaf(al0, a.x, fmaf(al1, b.x, acc.x));
        acc.y = fmaf(al0, a.y, fmaf(al1, b.y, acc.y));
        acc.z = fmaf(al0, a.z, fmaf(al1, b.z, acc.z));
        acc.w = fmaf(al0, a.w, fmaf(al1, b.w, acc.w));
    }
    if (j < end) {
        float al = g_alphaP[j];
        int s0 = g_srcP[j];
        float4 a = ((const float4*)(cur + (size_t)s0 * DIM))[hl];
        acc.x = fmaf(al, a.x, acc.x);
        acc.y = fmaf(al, a.y, acc.y);
        acc.z = fmaf(al, a.z, acc.z);
        acc.w = fmaf(al, a.w, acc.w);
    }
    size_t off = (size_t)v * DIM;
    if (layer < 2) {
        ((float4*)(sel_next(nextSel) + off))[hl] = acc;
        float4* ap = ((float4*)(g_acc + off)) + hl;
        if (layer == 0) {
            *ap = acc;
        } else {
            float4 a = *ap;
            a.x += acc.x; a.y += acc.y; a.z += acc.z; a.w += acc.w;
            *ap = a;
        }
    } else {
        float4 a  = ((const float4*)(g_acc + off))[hl];
        float4 e0 = ((const float4*)(emb_in + off))[hl];
        ((float4*)(out + off))[hl] = make_float4(
            (e0.x + a.x + acc.x) * 0.25f, (e0.y + a.y + acc.y) * 0.25f,
            (e0.z + a.z + acc.z) * 0.25f, (e0.w + a.w + acc.w) * 0.25f);
    }
}

extern "C" void kernel_launch(void* const* d_in, const int* in_sizes, int n_in,
                              void* d_out, int out_size) {
    const int*   ei    = (const int*)d_in[0];
    const float* ea    = (const float*)d_in[1];
    const float* emb   = (const float*)d_in[2];
    const float* W     = (const float*)d_in[3];
    const float* bias  = (const float*)d_in[4];
    const float* scale = (const float*)d_in[5];

    int E  = in_sizes[1];
    int ND = in_sizes[2];
    int N  = ND / DIM;

    const int T = 256;
    int blk_n   = (N + T - 1) / T;
    int blk_e   = (E + T - 1) / T;
    int blk_n32 = (N * 32 + T - 1) / T;       // warp per node
    int nwarp2  = (N + 1) / 2;                // 2 nodes per warp
    int blk_n16 = (nwarp2 * 32 + T - 1) / T;

    // ---- build both CSRs (edge_index is constant across the launch) ----
    k_cnt_zero<<<blk_n, T>>>(N);
    k_hist<<<blk_e, T>>>(ei, E);
    for (int w = 0; w < 2; w++) {
        k_scan1<<<blk_n, 256>>>(w, N);
        k_scan2<<<1, 1024>>>(w, blk_n);
        k_scan3<<<blk_n, T>>>(w, N, E);
    }
    k_scatter<<<blk_e, T>>>(ei, ea, scale, E);

    const int curSel[3]  = {0, 1, 2};
    const int nextSel[3] = {1, 2, 1};

    float* out = (float*)d_out;
    float* out2 = out;
    if (out_size >= 2 * ND) {
        cudaMemcpyAsync(out, emb, (size_t)ND * sizeof(float),
                        cudaMemcpyDeviceToDevice, 0);
        out2 = out + ND;
    }

    for (int l = 0; l < 3; l++) {
        k_gemm64<<<(N + 31) / 32, T>>>(curSel[l], emb, W + (size_t)l * DIM * DIM, N);
        k_score_softmax<<<blk_n32, T>>>(curSel[l], emb, bias, N, l);
        k_aggregate<<<blk_n16, T>>>(curSel[l], emb, nextSel[l], out2, N, l);
    }
}

// round 9
// speedup vs baseline: 1.0248x; 1.0248x over previous
#include <cuda_runtime.h>
#include <cuda_bf16.h>

// Problem constants: N=150000 nodes, E=1e6 edges, D=64, 3 layers.
#define NMAX   150016
#define EMAX   1000448
#define DIM    64
#define SOFTEPS 1e-16f
#define NEGINF __int_as_float(0xff800000)

// Scratch (no allocations allowed -> __device__ globals).
__device__ float g_Z[NMAX * DIM];
__device__ float g_bufA[NMAX * DIM];
__device__ float g_bufB[NMAX * DIM];
__device__ float g_alphaP[EMAX];   // alpha, in dst-CSR order
// dst-CSR (gather-aggregate)
__device__ int g_cntD[NMAX], g_rsD[NMAX + 1], g_curD[NMAX];
__device__ int g_srcP[EMAX];       // src node at dst-CSR slot
// src-CSR (fused score+softmax)
__device__ int g_cntS[NMAX], g_rsS[NMAX + 1], g_curS[NMAX];
__device__ int   g_dstS[EMAX];     // dst node at src-CSR slot
__device__ int   g_posDS[EMAX];    // src-CSR slot -> dst-CSR slot
__device__ float g_eterm[EMAX];    // 64*exp(scale*ea[e]) at src-CSR slot
__device__ int g_bsumD[1024], g_bsumS[1024];

__device__ __forceinline__ const float* sel_cur(int sel, const float* emb_in) {
    if (sel == 0) return emb_in;
    return (sel == 1) ? g_bufA : g_bufB;
}
__device__ __forceinline__ float* sel_next(int sel) {
    return (sel == 1) ? g_bufA : g_bufB;
}

// ---------------- CSR build (once per launch) ----------------
__global__ void k_cnt_zero(int N) {
    int i = blockIdx.x * blockDim.x + threadIdx.x;
    if (i < N) { g_cntD[i] = 0; g_cntS[i] = 0; }
}
__global__ void k_hist(const int* __restrict__ ei, int E) {
    int e = blockIdx.x * blockDim.x + threadIdx.x;
    if (e < E) {
        atomicAdd(&g_cntD[ei[E + e]], 1);
        atomicAdd(&g_cntS[ei[e]], 1);
    }
}
// Fused per-256-block exclusive scan over BOTH counter arrays.
__global__ void k_scan1(int N) {
    __shared__ int shD[256], shS[256];
    int i = blockIdx.x * 256 + threadIdx.x;
    int vD = (i < N) ? g_cntD[i] : 0;
    int vS = (i < N) ? g_cntS[i] : 0;
    shD[threadIdx.x] = vD;
    shS[threadIdx.x] = vS;
    __syncthreads();
    for (int o = 1; o < 256; o <<= 1) {
        int tD = (threadIdx.x >= o) ? shD[threadIdx.x - o] : 0;
        int tS = (threadIdx.x >= o) ? shS[threadIdx.x - o] : 0;
        __syncthreads();
        shD[threadIdx.x] += tD;
        shS[threadIdx.x] += tS;
        __syncthreads();
    }
    if (i < N) {
        g_rsD[i] = shD[threadIdx.x] - vD;
        g_rsS[i] = shS[threadIdx.x] - vS;
    }
    if (threadIdx.x == 255) {
        g_bsumD[blockIdx.x] = shD[255];
        g_bsumS[blockIdx.x] = shS[255];
    }
}
// Single-block exclusive scan of both block-sum arrays (nb <= 1024).
__global__ void k_scan2(int nb) {
    __shared__ int shD[1024], shS[1024];
    int t = threadIdx.x;
    int vD = (t < nb) ? g_bsumD[t] : 0;
    int vS = (t < nb) ? g_bsumS[t] : 0;
    shD[t] = vD;
    shS[t] = vS;
    __syncthreads();
    for (int o = 1; o < 1024; o <<= 1) {
        int uD = (t >= o) ? shD[t - o] : 0;
        int uS = (t >= o) ? shS[t - o] : 0;
        __syncthreads();
        shD[t] += uD;
        shS[t] += uS;
        __syncthreads();
    }
    if (t < nb) {
        g_bsumD[t] = shD[t] - vD;
        g_bsumS[t] = shS[t] - vS;
    }
}
__global__ void k_scan3(int N, int E) {
    int i = blockIdx.x * blockDim.x + threadIdx.x;
    if (i < N) {
        int rD = g_rsD[i] + g_bsumD[i >> 8];
        g_rsD[i] = rD;
        g_curD[i] = rD;
        int rS = g_rsS[i] + g_bsumS[i >> 8];
        g_rsS[i] = rS;
        g_curS[i] = rS;
    }
    if (i == 0) { g_rsD[N] = E; g_rsS[N] = E; }
}
__global__ void k_scatter(const int* __restrict__ ei, const float* __restrict__ ea,
                          const float* __restrict__ scale_p, int E) {
    int e = blockIdx.x * blockDim.x + threadIdx.x;
    if (e >= E) return;
    int src = ei[e], dst = ei[E + e];
    int pd = atomicAdd(&g_curD[dst], 1);
    g_srcP[pd] = src;
    int ps = atomicAdd(&g_curS[src], 1);
    g_dstS[ps]  = dst;
    g_posDS[ps] = pd;
    g_eterm[ps] = 64.0f * __expf(scale_p[0] * ea[e]);
}

// ---------------- per-layer kernels ----------------
// Z = cur @ W : 32 rows / 256-thread block, 8 outputs per thread.
__global__ void k_gemm64(int curSel, const float* __restrict__ emb_in,
                         const float* __restrict__ W, int N) {
    __shared__ float sW[DIM * DIM];
    __shared__ float sX[32 * 65];
    const float* X = sel_cur(curSel, emb_in);
    int tid = threadIdx.x;
    #pragma unroll
    for (int i = tid; i < DIM * DIM; i += 256) sW[i] = W[i];
    int rowBase = blockIdx.x * 32;
    #pragma unroll
    for (int i = tid; i < 32 * DIM; i += 256) {
        int r = i >> 6, c = i & 63;
        int row = rowBase + r;
        sX[r * 65 + c] = (row < N) ? X[(size_t)row * DIM + c] : 0.0f;
    }
    __syncthreads();
    int r  = tid >> 3;
    int cg = (tid & 7) * 8;
    float a0=0,a1=0,a2=0,a3=0,a4=0,a5=0,a6=0,a7=0;
    #pragma unroll
    for (int k = 0; k < DIM; k++) {
        float xv = sX[r * 65 + k];
        float4 w0 = *(const float4*)&sW[k * DIM + cg];
        float4 w1 = *(const float4*)&sW[k * DIM + cg + 4];
        a0 = fmaf(xv, w0.x, a0); a1 = fmaf(xv, w0.y, a1);
        a2 = fmaf(xv, w0.z, a2); a3 = fmaf(xv, w0.w, a3);
        a4 = fmaf(xv, w1.x, a4); a5 = fmaf(xv, w1.y, a5);
        a6 = fmaf(xv, w1.z, a6); a7 = fmaf(xv, w1.w, a7);
    }
    int row = rowBase + r;
    if (row < N) {
        float4* o = (float4*)&g_Z[(size_t)row * DIM + cg];
        o[0] = make_float4(a0, a1, a2, a3);
        o[1] = make_float4(a4, a5, a6, a7);
    }
}

// Fused edge-score + segment-softmax: one warp per src node (round-7 form).
// 16-lane halves, float4 lanes; half-scoped masks in deg-dependent loops.
__global__ void k_score_softmax(int curSel, const float* __restrict__ emb_in,
                                const float* __restrict__ bias_p, int N, int layer) {
    __shared__ float ssc[8][32];            // 8 warps/block
    int gt   = blockIdx.x * blockDim.x + threadIdx.x;
    int v    = gt >> 5;
    int lane = threadIdx.x & 31;
    int wid  = threadIdx.x >> 5;
    if (v >= N) return;
    int beg = g_rsS[v], end = g_rsS[v + 1];
    int deg = end - beg;
    if (deg == 0) return;
    const float* cur = sel_cur(curSel, emb_in);
    int half = lane >> 4;
    int hl   = lane & 15;
    unsigned hmask = 0xFFFFu << (half << 4);
    float4 x = ((const float4*)(cur + (size_t)v * DIM))[hl];
    float bias = bias_p[layer];

    if (deg <= 32) {
        for (int t2 = half; t2 < deg; t2 += 2) {
            int j = beg + t2;
            int dst = g_dstS[j];
            float4 z = ((const float4*)(g_Z + (size_t)dst * DIM))[hl];
            float p = z.x * x.x + z.y * x.y + z.z * x.z + z.w * x.w;
            #pragma unroll
            for (int o = 8; o; o >>= 1)
                p += __shfl_xor_sync(hmask, p, o, 16);
            float s = p + g_eterm[j] + bias;
            s = (s >= 0.0f) ? s : 0.2f * s;
            if (hl == 0) ssc[wid][t2] = s;
        }
        __syncwarp();
        float sv = (lane < deg) ? ssc[wid][lane] : NEGINF;
        float m = sv;
        #pragma unroll
        for (int o = 16; o; o >>= 1)
            m = fmaxf(m, __shfl_xor_sync(0xffffffffu, m, o));
        float ex = (lane < deg) ? __expf(sv - m) : 0.0f;
        float den = ex;
        #pragma unroll
        for (int o = 16; o; o >>= 1)
            den += __shfl_xor_sync(0xffffffffu, den, o);
        if (lane < deg)
            g_alphaP[g_posDS[beg + lane]] = ex / (den + SOFTEPS);
    } else {
        // Rare fallback (deg>32): 3 passes, recompute.
        float mloc = NEGINF;
        for (int t2 = half; t2 < deg; t2 += 2) {
            int j = beg + t2;
            int dst = g_dstS[j];
            float4 z = ((const float4*)(g_Z + (size_t)dst * DIM))[hl];
            float p = z.x * x.x + z.y * x.y + z.z * x.z + z.w * x.w;
            #pragma unroll
            for (int o = 8; o; o >>= 1)
                p += __shfl_xor_sync(hmask, p, o, 16);
            float s = p + g_eterm[j] + bias;
            s = (s >= 0.0f) ? s : 0.2f * s;
            mloc = fmaxf(mloc, s);
        }
        #pragma unroll
        for (int o = 16; o; o >>= 1)
            mloc = fmaxf(mloc, __shfl_xor_sync(0xffffffffu, mloc, o));
        float dloc = 0.0f;
        for (int t2 = half; t2 < deg; t2 += 2) {
            int j = beg + t2;
            int dst = g_dstS[j];
            float4 z = ((const float4*)(g_Z + (size_t)dst * DIM))[hl];
            float p = z.x * x.x + z.y * x.y + z.z * x.z + z.w * x.w;
            #pragma unroll
            for (int o = 8; o; o >>= 1)
                p += __shfl_xor_sync(hmask, p, o, 16);
            float s = p + g_eterm[j] + bias;
            s = (s >= 0.0f) ? s : 0.2f * s;
            dloc += __expf(s - mloc);
        }
        #pragma unroll
        for (int o = 16; o; o >>= 1)
            dloc += __shfl_xor_sync(0xffffffffu, dloc, o);
        float den = dloc * 0.0625f;         // /16
        float inv = 1.0f / (den + SOFTEPS);
        for (int t2 = half; t2 < deg; t2 += 2) {
            int j = beg + t2;
            int dst = g_dstS[j];
            float4 z = ((const float4*)(g_Z + (size_t)dst * DIM))[hl];
            float p = z.x * x.x + z.y * x.y + z.z * x.z + z.w * x.w;
            #pragma unroll
            for (int o = 8; o; o >>= 1)
                p += __shfl_xor_sync(hmask, p, o, 16);
            float s = p + g_eterm[j] + bias;
            s = (s >= 0.0f) ? s : 0.2f * s;
            if (hl == 0)
                g_alphaP[g_posDS[j]] = __expf(s - mloc) * inv;
        }
    }
}

// Gather-aggregate: warp per dst node (round-7 form), float2 lanes, unroll 4.
// layer<2: write next only. layer==2: out = (emb + bufA + bufB + agg)/4.
__global__ void k_aggregate(int curSel, const float* __restrict__ emb_in,
                            int nextSel, float* __restrict__ out,
                            int N, int layer) {
    int warp = (blockIdx.x * blockDim.x + threadIdx.x) >> 5;
    int lane = threadIdx.x & 31;
    if (warp >= N) return;
    const float* cur = sel_cur(curSel, emb_in);
    int beg = g_rsD[warp];
    int end = g_rsD[warp + 1];
    float ax = 0.0f, ay = 0.0f;
    int j = beg;
    for (; j + 4 <= end; j += 4) {
        float al0 = g_alphaP[j],     al1 = g_alphaP[j + 1];
        float al2 = g_alphaP[j + 2], al3 = g_alphaP[j + 3];
        int s0 = g_srcP[j],     s1 = g_srcP[j + 1];
        int s2 = g_srcP[j + 2], s3 = g_srcP[j + 3];
        float2 x0 = ((const float2*)(cur + (size_t)s0 * DIM))[lane];
        float2 x1 = ((const float2*)(cur + (size_t)s1 * DIM))[lane];
        float2 x2 = ((const float2*)(cur + (size_t)s2 * DIM))[lane];
        float2 x3 = ((const float2*)(cur + (size_t)s3 * DIM))[lane];
        ax = fmaf(al0, x0.x, fmaf(al1, x1.x, fmaf(al2, x2.x, fmaf(al3, x3.x, ax))));
        ay = fmaf(al0, x0.y, fmaf(al1, x1.y, fmaf(al2, x2.y, fmaf(al3, x3.y, ay))));
    }
    for (; j < end; j++) {
        float al = g_alphaP[j];
        int s0 = g_srcP[j];
        float2 x0 = ((const float2*)(cur + (size_t)s0 * DIM))[lane];
        ax = fmaf(al, x0.x, ax);
        ay = fmaf(al, x0.y, ay);
    }
    size_t off = (size_t)warp * DIM;
    if (layer < 2) {
        ((float2*)(sel_next(nextSel) + off))[lane] = make_float2(ax, ay);
    } else {
        float2 a  = ((const float2*)(g_bufA + off))[lane];
        float2 b  = ((const float2*)(g_bufB + off))[lane];
        float2 e0 = ((const float2*)(emb_in + off))[lane];
        ((float2*)(out + off))[lane] = make_float2(
            (e0.x + a.x + b.x + ax) * 0.25f,
            (e0.y + a.y + b.y + ay) * 0.25f);
    }
}

extern "C" void kernel_launch(void* const* d_in, const int* in_sizes, int n_in,
                              void* d_out, int out_size) {
    const int*   ei    = (const int*)d_in[0];
    const float* ea    = (const float*)d_in[1];
    const float* emb   = (const float*)d_in[2];
    const float* W     = (const float*)d_in[3];
    const float* bias  = (const float*)d_in[4];
    const float* scale = (const float*)d_in[5];

    int E  = in_sizes[1];
    int ND = in_sizes[2];
    int N  = ND / DIM;

    const int T = 256;
    int blk_n   = (N + T - 1) / T;
    int blk_e   = (E + T - 1) / T;
    int blk_n32 = (N * 32 + T - 1) / T;       // warp per node

    // ---- build both CSRs (fused scans; edge_index constant per launch) ----
    k_cnt_zero<<<blk_n, T>>>(N);
    k_hist<<<blk_e, T>>>(ei, E);
    k_scan1<<<blk_n, 256>>>(N);
    k_scan2<<<1, 1024>>>(blk_n);
    k_scan3<<<blk_n, T>>>(N, E);
    k_scatter<<<blk_e, T>>>(ei, ea, scale, E);

    const int curSel[3]  = {0, 1, 2};
    const int nextSel[3] = {1, 2, 1};

    float* out = (float*)d_out;
    float* out2 = out;
    if (out_size >= 2 * ND) {
        cudaMemcpyAsync(out, emb, (size_t)ND * sizeof(float),
                        cudaMemcpyDeviceToDevice, 0);
        out2 = out + ND;
    }

    for (int l = 0; l < 3; l++) {
        k_gemm64<<<(N + 31) / 32, T>>>(curSel[l], emb, W + (size_t)l * DIM * DIM, N);
        k_score_softmax<<<blk_n32, T>>>(curSel[l], emb, bias, N, l);
        k_aggregate<<<blk_n32, T>>>(curSel[l], emb, nextSel[l], out2, N, l);
    }
}

// round 10
// speedup vs baseline: 1.1595x; 1.1314x over previous
#include <cuda_runtime.h>
#include <cuda_bf16.h>

// Problem constants: N=150000 nodes, E=1e6 edges, D=64, 3 layers.
#define NMAX   150016
#define EMAX   1000448
#define DIM    64
#define SOFTEPS 1e-16f
#define NEGINF __int_as_float(0xff800000)

// Scratch (no allocations allowed -> __device__ globals).
__device__ float g_Z[NMAX * DIM];
__device__ float g_bufA[NMAX * DIM];
__device__ float g_bufB[NMAX * DIM];
// src-CSR only (score+softmax+scatter all group by src)
__device__ int   g_cntS[NMAX], g_rsS[NMAX + 1], g_curS[NMAX];
__device__ int   g_dstS[EMAX];     // dst node at src-CSR slot
__device__ float g_eterm[EMAX];    // 64*exp(scale*ea[e]) at src-CSR slot
__device__ int   g_bsumS[1024];

__device__ __forceinline__ const float* sel_cur(int sel, const float* emb_in) {
    if (sel == 0) return emb_in;
    return (sel == 1) ? g_bufA : g_bufB;
}

// ---------------- CSR build (once per launch; src side only) ----------------
__global__ void k_cnt_zero(int N) {
    int i = blockIdx.x * blockDim.x + threadIdx.x;
    if (i < N) g_cntS[i] = 0;
}
__global__ void k_hist(const int* __restrict__ ei, int E) {
    int e = blockIdx.x * blockDim.x + threadIdx.x;
    if (e < E) atomicAdd(&g_cntS[ei[e]], 1);
}
__global__ void k_scan1(int N) {
    __shared__ int sh[256];
    int i = blockIdx.x * 256 + threadIdx.x;
    int v = (i < N) ? g_cntS[i] : 0;
    sh[threadIdx.x] = v;
    __syncthreads();
    for (int o = 1; o < 256; o <<= 1) {
        int t = (threadIdx.x >= o) ? sh[threadIdx.x - o] : 0;
        __syncthreads();
        sh[threadIdx.x] += t;
        __syncthreads();
    }
    if (i < N) g_rsS[i] = sh[threadIdx.x] - v;
    if (threadIdx.x == 255) g_bsumS[blockIdx.x] = sh[255];
}
__global__ void k_scan2(int nb) {
    __shared__ int sh[1024];
    int t = threadIdx.x;
    int v = (t < nb) ? g_bsumS[t] : 0;
    sh[t] = v;
    __syncthreads();
    for (int o = 1; o < 1024; o <<= 1) {
        int u = (t >= o) ? sh[t - o] : 0;
        __syncthreads();
        sh[t] += u;
        __syncthreads();
    }
    if (t < nb) g_bsumS[t] = sh[t] - v;
}
__global__ void k_scan3(int N, int E) {
    int i = blockIdx.x * blockDim.x + threadIdx.x;
    if (i < N) {
        int r = g_rsS[i] + g_bsumS[i >> 8];
        g_rsS[i] = r;
        g_curS[i] = r;
    }
    if (i == 0) g_rsS[N] = E;
}
__global__ void k_scatter(const int* __restrict__ ei, const float* __restrict__ ea,
                          const float* __restrict__ scale_p, int E) {
    int e = blockIdx.x * blockDim.x + threadIdx.x;
    if (e >= E) return;
    int src = ei[e], dst = ei[E + e];
    int ps = atomicAdd(&g_curS[src], 1);
    g_dstS[ps]  = dst;
    g_eterm[ps] = 64.0f * __expf(scale_p[0] * ea[e]);
}

// ---------------- per-layer kernels ----------------
// Z = cur @ W (32 rows/block, 8 outputs/thread). Also prepares the scatter
// target for its 32 rows: zeroes next (l<2) or prefills out=(emb+A+B)/4 (l==2).
__global__ void k_gemm64(int curSel, const float* __restrict__ emb_in,
                         const float* __restrict__ W, float* __restrict__ out,
                         int N, int layer) {
    __shared__ float sW[DIM * DIM];
    __shared__ float sX[32 * 65];
    const float* X = sel_cur(curSel, emb_in);
    int tid = threadIdx.x;
    #pragma unroll
    for (int i = tid; i < DIM * DIM; i += 256) sW[i] = W[i];
    int rowBase = blockIdx.x * 32;
    #pragma unroll
    for (int i = tid; i < 32 * DIM; i += 256) {
        int r = i >> 6, c = i & 63;
        int row = rowBase + r;
        sX[r * 65 + c] = (row < N) ? X[(size_t)row * DIM + c] : 0.0f;
    }
    // Prepare scatter target for this block's rows (32*16 float4 slots).
    if (layer < 2) {
        float* nxt = (layer == 0) ? g_bufA : g_bufB;
        for (int i = tid; i < 32 * 16; i += 256) {
            int row = rowBase + (i >> 4);
            if (row < N)
                ((float4*)(nxt + (size_t)row * DIM))[i & 15] =
                    make_float4(0.f, 0.f, 0.f, 0.f);
        }
    } else {
        for (int i = tid; i < 32 * 16; i += 256) {
            int row = rowBase + (i >> 4);
            if (row < N) {
                size_t off = (size_t)row * DIM;
                float4 e0 = ((const float4*)(emb_in + off))[i & 15];
                float4 a  = ((const float4*)(g_bufA + off))[i & 15];
                float4 b  = ((const float4*)(g_bufB + off))[i & 15];
                ((float4*)(out + off))[i & 15] = make_float4(
                    (e0.x + a.x + b.x) * 0.25f, (e0.y + a.y + b.y) * 0.25f,
                    (e0.z + a.z + b.z) * 0.25f, (e0.w + a.w + b.w) * 0.25f);
            }
        }
    }
    __syncthreads();
    int r  = tid >> 3;
    int cg = (tid & 7) * 8;
    float a0=0,a1=0,a2=0,a3=0,a4=0,a5=0,a6=0,a7=0;
    #pragma unroll
    for (int k = 0; k < DIM; k++) {
        float xv = sX[r * 65 + k];
        float4 w0 = *(const float4*)&sW[k * DIM + cg];
        float4 w1 = *(const float4*)&sW[k * DIM + cg + 4];
        a0 = fmaf(xv, w0.x, a0); a1 = fmaf(xv, w0.y, a1);
        a2 = fmaf(xv, w0.z, a2); a3 = fmaf(xv, w0.w, a3);
        a4 = fmaf(xv, w1.x, a4); a5 = fmaf(xv, w1.y, a5);
        a6 = fmaf(xv, w1.z, a6); a7 = fmaf(xv, w1.w, a7);
    }
    int row = rowBase + r;
    if (row < N) {
        float4* o = (float4*)&g_Z[(size_t)row * DIM + cg];
        o[0] = make_float4(a0, a1, a2, a3);
        o[1] = make_float4(a4, a5, a6, a7);
    }
}

// Fused score + segment-softmax + scatter-aggregate: one warp per src node.
// x = cur[v] in registers; gather Z[dst] per edge (the only row gather);
// softmax in-warp; scatter cscale*alpha*x via float4 atomics.
// out_t==nullptr -> target is g_bufA (layer 0) / g_bufB (layer 1).
// Half-scoped shuffle masks in deg-dependent loops (odd-deg safety).
__global__ void k_fused(int curSel, const float* __restrict__ emb_in,
                        const float* __restrict__ bias_p,
                        float* out_t, float cscale, int N, int layer) {
    __shared__ float ssc[8][32];            // 8 warps/block
    int gt   = blockIdx.x * blockDim.x + threadIdx.x;
    int v    = gt >> 5;
    int lane = threadIdx.x & 31;
    int wid  = threadIdx.x >> 5;
    if (v >= N) return;
    int beg = g_rsS[v], end = g_rsS[v + 1];
    int deg = end - beg;
    if (deg == 0) return;
    float* target = out_t ? out_t : ((layer == 0) ? g_bufA : g_bufB);
    const float* cur = sel_cur(curSel, emb_in);
    int half = lane >> 4;
    int hl   = lane & 15;
    unsigned hmask = 0xFFFFu << (half << 4);
    float4 x = ((const float4*)(cur + (size_t)v * DIM))[hl];
    float bias = bias_p[layer];

    if (deg <= 32) {
        for (int t2 = half; t2 < deg; t2 += 2) {
            int j = beg + t2;
            int dst = g_dstS[j];
            float4 z = ((const float4*)(g_Z + (size_t)dst * DIM))[hl];
            float p = z.x * x.x + z.y * x.y + z.z * x.z + z.w * x.w;
            #pragma unroll
            for (int o = 8; o; o >>= 1)
                p += __shfl_xor_sync(hmask, p, o, 16);
            float s = p + g_eterm[j] + bias;
            s = (s >= 0.0f) ? s : 0.2f * s;
            if (hl == 0) ssc[wid][t2] = s;
        }
        __syncwarp();
        float sv = (lane < deg) ? ssc[wid][lane] : NEGINF;
        float m = sv;
        #pragma unroll
        for (int o = 16; o; o >>= 1)
            m = fmaxf(m, __shfl_xor_sync(0xffffffffu, m, o));
        float ex = (lane < deg) ? __expf(sv - m) : 0.0f;
        float den = ex;
        #pragma unroll
        for (int o = 16; o; o >>= 1)
            den += __shfl_xor_sync(0xffffffffu, den, o);
        if (lane < deg)
            ssc[wid][lane] = ex / (den + SOFTEPS) * cscale;
        __syncwarp();
        for (int t2 = half; t2 < deg; t2 += 2) {
            int j = beg + t2;
            float al = ssc[wid][t2];
            int dst = g_dstS[j];
            atomicAdd(((float4*)(target + (size_t)dst * DIM)) + hl,
                      make_float4(al * x.x, al * x.y, al * x.z, al * x.w));
        }
    } else {
        // Rare fallback (deg>32): 3 passes, recompute; scatter inline in pass 3.
        float mloc = NEGINF;
        for (int t2 = half; t2 < deg; t2 += 2) {
            int j = beg + t2;
            int dst = g_dstS[j];
            float4 z = ((const float4*)(g_Z + (size_t)dst * DIM))[hl];
            float p = z.x * x.x + z.y * x.y + z.z * x.z + z.w * x.w;
            #pragma unroll
            for (int o = 8; o; o >>= 1)
                p += __shfl_xor_sync(hmask, p, o, 16);
            float s = p + g_eterm[j] + bias;
            s = (s >= 0.0f) ? s : 0.2f * s;
            mloc = fmaxf(mloc, s);
        }
        #pragma unroll
        for (int o = 16; o; o >>= 1)
            mloc = fmaxf(mloc, __shfl_xor_sync(0xffffffffu, mloc, o));
        float dloc = 0.0f;
        for (int t2 = half; t2 < deg; t2 += 2) {
            int j = beg + t2;
            int dst = g_dstS[j];
            float4 z = ((const float4*)(g_Z + (size_t)dst * DIM))[hl];
            float p = z.x * x.x + z.y * x.y + z.z * x.z + z.w * x.w;
            #pragma unroll
            for (int o = 8; o; o >>= 1)
                p += __shfl_xor_sync(hmask, p, o, 16);
            float s = p + g_eterm[j] + bias;
            s = (s >= 0.0f) ? s : 0.2f * s;
            dloc += __expf(s - mloc);
        }
        #pragma unroll
        for (int o = 16; o; o >>= 1)
            dloc += __shfl_xor_sync(0xffffffffu, dloc, o);
        float den = dloc * 0.0625f;         // /16 (each edge counted by 16 lanes)
        float inv = cscale / (den + SOFTEPS);
        for (int t2 = half; t2 < deg; t2 += 2) {
            int j = beg + t2;
            int dst = g_dstS[j];
            float4 z = ((const float4*)(g_Z + (size_t)dst * DIM))[hl];
            float p = z.x * x.x + z.y * x.y + z.z * x.z + z.w * x.w;
            #pragma unroll
            for (int o = 8; o; o >>= 1)
                p += __shfl_xor_sync(hmask, p, o, 16);
            float s = p + g_eterm[j] + bias;
            s = (s >= 0.0f) ? s : 0.2f * s;
            float al = __expf(s - mloc) * inv;  // uniform across the half
            atomicAdd(((float4*)(target + (size_t)dst * DIM)) + hl,
                      make_float4(al * x.x, al * x.y, al * x.z, al * x.w));
        }
    }
}

extern "C" void kernel_launch(void* const* d_in, const int* in_sizes, int n_in,
                              void* d_out, int out_size) {
    const int*   ei    = (const int*)d_in[0];
    const float* ea    = (const float*)d_in[1];
    const float* emb   = (const float*)d_in[2];
    const float* W     = (const float*)d_in[3];
    const float* bias  = (const float*)d_in[4];
    const float* scale = (const float*)d_in[5];

    int E  = in_sizes[1];
    int ND = in_sizes[2];
    int N  = ND / DIM;

    const int T = 256;
    int blk_n   = (N + T - 1) / T;
    int blk_e   = (E + T - 1) / T;
    int blk_n32 = (N * 32 + T - 1) / T;       // warp per node

    // ---- build src-CSR (edge_index constant per launch) ----
    k_cnt_zero<<<blk_n, T>>>(N);
    k_hist<<<blk_e, T>>>(ei, E);
    k_scan1<<<blk_n, 256>>>(N);
    k_scan2<<<1, 1024>>>(blk_n);
    k_scan3<<<blk_n, T>>>(N, E);
    k_scatter<<<blk_e, T>>>(ei, ea, scale, E);

    float* out = (float*)d_out;
    float* out2 = out;
    if (out_size >= 2 * ND) {
        cudaMemcpyAsync(out, emb, (size_t)ND * sizeof(float),
                        cudaMemcpyDeviceToDevice, 0);
        out2 = out + ND;
    }

    // Layer schedule: cur: emb -> A -> B; scatter target: A, B, out2.
    const int curSel[3] = {0, 1, 2};
    for (int l = 0; l < 3; l++) {
        k_gemm64<<<(N + 31) / 32, T>>>(curSel[l], emb,
                                       W + (size_t)l * DIM * DIM, out2, N, l);
        k_fused<<<blk_n32, T>>>(curSel[l], emb, bias,
                                (l == 2) ? out2 : nullptr,
                                (l == 2) ? 0.25f : 1.0f, N, l);
    }
}